// round 1
// baseline (speedup 1.0000x reference)
#include <cuda_runtime.h>
#include <math.h>

#define B_  16
#define S_  2048
#define D_  256
#define BQ  32
#define TK  128
#define NT  256

// shared layout (floats)
#define QS_OFF 0                       // Qs [32][256]           = 8192
#define KS_OFF 8192                    // Ks [32][128]           = 4096
#define PS_OFF (8192 + 4096)           // Ps [32][132]           = 4224
#define VS_OFF (8192 + 4096 + 4224)    // Vs [32][256] / Ts[32][257] = 8224
#define PS_STRIDE 132
#define SMEM_FLOATS (VS_OFF + 32 * 257)
#define SMEM_BYTES  (SMEM_FLOATS * 4)

__global__ void __launch_bounds__(NT, 2)
attn_flash_fp32(const float* __restrict__ q,
                const float* __restrict__ k,
                const float* __restrict__ v,
                const int*   __restrict__ mask,
                float* __restrict__ out)
{
    extern __shared__ float sm[];
    float* Qs = sm + QS_OFF;
    float* Ks = sm + KS_OFF;
    float* Ps = sm + PS_OFF;
    float* Vs = sm + VS_OFF;

    const int tid  = threadIdx.x;
    const int lane = tid & 31;
    const int warp = tid >> 5;
    const int b    = blockIdx.y;
    const int q0   = blockIdx.x * BQ;

    const float* qb_ptr = q + (size_t)b * S_ * D_ + (size_t)q0 * D_;
    const float* kb_ptr = k + (size_t)b * D_ * S_;
    const float* vb_ptr = v + (size_t)b * S_ * D_;
    const int*   mb_ptr = mask + (size_t)b * S_;

    // ---- load Q tile [32][256] into shared (coalesced float4) ----
    {
        int r  = tid >> 3;          // 0..31
        int c0 = (tid & 7) * 32;    // 8 threads per row, 32 floats each
        const float4* src = (const float4*)(qb_ptr + (size_t)r * D_ + c0);
        float4* dst = (float4*)(Qs + r * D_ + c0);
        #pragma unroll
        for (int i = 0; i < 8; i++) dst[i] = src[i];
    }

    const int qb4 = warp * 4;   // this warp owns q rows qb4..qb4+3 (both phases)
    const int jb  = lane * 4;   // phase A: this lane's 4 key columns
    const int db  = lane * 8;   // phase C: this lane's 8 d columns

    float O[4][8];
    #pragma unroll
    for (int a = 0; a < 4; a++)
        #pragma unroll
        for (int c = 0; c < 8; c++) O[a][c] = 0.f;

    float mrow[4] = {-INFINITY, -INFINITY, -INFINITY, -INFINITY};
    float lrow[4] = {0.f, 0.f, 0.f, 0.f};

    for (int kt = 0; kt < S_; kt += TK) {
        // ================= Phase A: S = Q @ K  (32 x 128) =================
        float s[4][4];
        #pragma unroll
        for (int a = 0; a < 4; a++)
            #pragma unroll
            for (int j = 0; j < 4; j++) s[a][j] = 0.f;

        for (int dc = 0; dc < D_; dc += 32) {
            __syncthreads();
            {   // load Ks [32 d][128 j]
                int r  = tid >> 3;
                int c0 = (tid & 7) * 16;
                const float4* src = (const float4*)(kb_ptr + (size_t)(dc + r) * S_ + kt + c0);
                float4* dst = (float4*)(Ks + r * TK + c0);
                #pragma unroll
                for (int i = 0; i < 4; i++) dst[i] = src[i];
            }
            __syncthreads();

            #pragma unroll
            for (int d4 = 0; d4 < 8; d4++) {
                float A[4][4];
                #pragma unroll
                for (int a = 0; a < 4; a++)
                    *(float4*)A[a] = *(const float4*)(Qs + (qb4 + a) * D_ + dc + d4 * 4);
                #pragma unroll
                for (int ii = 0; ii < 4; ii++) {
                    float4 bb = *(const float4*)(Ks + (d4 * 4 + ii) * TK + jb);
                    #pragma unroll
                    for (int a = 0; a < 4; a++) {
                        s[a][0] += A[a][ii] * bb.x;
                        s[a][1] += A[a][ii] * bb.y;
                        s[a][2] += A[a][ii] * bb.z;
                        s[a][3] += A[a][ii] * bb.w;
                    }
                }
            }
        }

        // ================= Phase B: mask + online softmax (warp-local) =====
        {
            int4 mv = *(const int4*)(mb_ptr + kt + jb);
            #pragma unroll
            for (int a = 0; a < 4; a++) {
                s[a][0] = mv.x ? s[a][0] : -1.0e9f;
                s[a][1] = mv.y ? s[a][1] : -1.0e9f;
                s[a][2] = mv.z ? s[a][2] : -1.0e9f;
                s[a][3] = mv.w ? s[a][3] : -1.0e9f;
            }
        }

        #pragma unroll
        for (int a = 0; a < 4; a++) {
            float rm = fmaxf(fmaxf(s[a][0], s[a][1]), fmaxf(s[a][2], s[a][3]));
            #pragma unroll
            for (int off = 16; off > 0; off >>= 1)
                rm = fmaxf(rm, __shfl_xor_sync(0xffffffffu, rm, off));
            float mnew = fmaxf(mrow[a], rm);
            float sc   = __expf(mrow[a] - mnew);
            mrow[a] = mnew;

            float p0 = __expf(s[a][0] - mnew);
            float p1 = __expf(s[a][1] - mnew);
            float p2 = __expf(s[a][2] - mnew);
            float p3 = __expf(s[a][3] - mnew);

            float rs = (p0 + p1) + (p2 + p3);
            #pragma unroll
            for (int off = 16; off > 0; off >>= 1)
                rs += __shfl_xor_sync(0xffffffffu, rs, off);
            lrow[a] = lrow[a] * sc + rs;

            // P tile (warp-private rows, conflict-free float4 stores)
            *(float4*)(Ps + (qb4 + a) * PS_STRIDE + jb) = make_float4(p0, p1, p2, p3);

            // rescale running O
            #pragma unroll
            for (int c = 0; c < 8; c++) O[a][c] *= sc;
        }
        __syncwarp();

        // ================= Phase C: O += P @ V =================
        for (int jc = 0; jc < TK; jc += 32) {
            __syncthreads();
            {   // load Vs [32 j][256 d]
                int r  = tid >> 3;
                int c0 = (tid & 7) * 32;
                const float4* src = (const float4*)(vb_ptr + (size_t)(kt + jc + r) * D_ + c0);
                float4* dst = (float4*)(Vs + r * D_ + c0);
                #pragma unroll
                for (int i = 0; i < 8; i++) dst[i] = src[i];
            }
            __syncthreads();

            #pragma unroll
            for (int j4 = 0; j4 < 8; j4++) {
                float P[4][4];
                #pragma unroll
                for (int a = 0; a < 4; a++)
                    *(float4*)P[a] = *(const float4*)(Ps + (qb4 + a) * PS_STRIDE + jc + j4 * 4);
                #pragma unroll
                for (int ji = 0; ji < 4; ji++) {
                    float4 v0 = *(const float4*)(Vs + (j4 * 4 + ji) * D_ + db);
                    float4 v1 = *(const float4*)(Vs + (j4 * 4 + ji) * D_ + db + 4);
                    #pragma unroll
                    for (int a = 0; a < 4; a++) {
                        O[a][0] += P[a][ji] * v0.x;
                        O[a][1] += P[a][ji] * v0.y;
                        O[a][2] += P[a][ji] * v0.z;
                        O[a][3] += P[a][ji] * v0.w;
                        O[a][4] += P[a][ji] * v1.x;
                        O[a][5] += P[a][ji] * v1.y;
                        O[a][6] += P[a][ji] * v1.z;
                        O[a][7] += P[a][ji] * v1.w;
                    }
                }
            }
        }
    }

    // ================= Epilogue: normalize, /16, transpose, store ==========
    float inv[4];
    #pragma unroll
    for (int a = 0; a < 4; a++) inv[a] = 1.f / (lrow[a] * 16.0f);

    __syncthreads();  // done reading Vs; reuse as transpose staging Ts[32][257]
    #pragma unroll
    for (int a = 0; a < 4; a++)
        #pragma unroll
        for (int c = 0; c < 8; c++)
            Vs[(qb4 + a) * 257 + db + c] = O[a][c] * inv[a];
    __syncthreads();

    // out[b][d][q]: warp w writes d rows {w, w+8, ...}, lanes = consecutive q
    {
        float* ob = out + (size_t)b * D_ * S_ + q0;
        for (int dr = warp; dr < D_; dr += 8)
            ob[(size_t)dr * S_ + lane] = Vs[lane * 257 + dr];
    }
}

extern "C" void kernel_launch(void* const* d_in, const int* in_sizes, int n_in,
                              void* d_out, int out_size)
{
    (void)in_sizes; (void)n_in; (void)out_size;
    const float* q    = (const float*)d_in[0];
    const float* k    = (const float*)d_in[1];
    const float* v    = (const float*)d_in[2];
    const int*   mask = (const int*)d_in[3];
    float* out = (float*)d_out;

    cudaFuncSetAttribute(attn_flash_fp32,
                         cudaFuncAttributeMaxDynamicSharedMemorySize, SMEM_BYTES);

    dim3 grid(S_ / BQ, B_);
    attn_flash_fp32<<<grid, NT, SMEM_BYTES>>>(q, k, v, mask, out);
}

// round 3
// speedup vs baseline: 1.1028x; 1.1028x over previous
#include <cuda_runtime.h>
#include <math.h>

#define B_  16
#define S_  2048
#define D_  256
#define BQ  32
#define TK  256
#define NT  256

// shared layout (floats)
#define QT_OFF 0                        // Qt [256 d][32 q]   = 8192
#define KS_OFF 8192                     // Ks [16 d][256 j]   = 4096
#define PS_OFF (8192 + 4096)            // Ps [32 q][260]     = 8320
#define VS_OFF (8192 + 4096 + 8320)     // Vs [32 j][256 d]   = 8192
#define PS_STRIDE 260
#define SMEM_FLOATS (VS_OFF + 32 * 256)
#define SMEM_BYTES  (SMEM_FLOATS * 4)

__global__ void __launch_bounds__(NT, 2)
attn_flash_fp32(const float* __restrict__ q,
                const float* __restrict__ k,
                const float* __restrict__ v,
                const int*   __restrict__ mask,
                float* __restrict__ out)
{
    extern __shared__ float sm[];
    float* Qt = sm + QT_OFF;
    float* Ks = sm + KS_OFF;
    float* Ps = sm + PS_OFF;
    float* Vs = sm + VS_OFF;

    const int tid  = threadIdx.x;
    const int lane = tid & 31;
    const int warp = tid >> 5;
    const int b    = blockIdx.y;
    const int q0   = blockIdx.x * BQ;

    const float* qb_ptr = q + (size_t)b * S_ * D_ + (size_t)q0 * D_;
    const float* kb_ptr = k + (size_t)b * D_ * S_;
    const float* vb_ptr = v + (size_t)b * S_ * D_;
    const int*   mb_ptr = mask + (size_t)b * S_;

    // ---- load Q tile TRANSPOSED into shared: Qt[d][q] ----
    {
        int r  = tid >> 3;          // q row 0..31
        int c0 = (tid & 7) * 32;    // d chunk
        const float4* src = (const float4*)(qb_ptr + (size_t)r * D_ + c0);
        #pragma unroll
        for (int i = 0; i < 8; i++) {
            float4 t = src[i];
            int c = c0 + i * 4;
            Qt[(c + 0) * 32 + r] = t.x;
            Qt[(c + 1) * 32 + r] = t.y;
            Qt[(c + 2) * 32 + r] = t.z;
            Qt[(c + 3) * 32 + r] = t.w;
        }
    }

    const int qb4 = warp * 4;   // this warp owns q rows qb4..qb4+3
    const int jb  = lane * 4;   // lane's j/d columns: jb..jb+3 and 128+jb..128+jb+3

    float O[4][8];
    #pragma unroll
    for (int a = 0; a < 4; a++)
        #pragma unroll
        for (int c = 0; c < 8; c++) O[a][c] = 0.f;

    float mrow[4] = {-INFINITY, -INFINITY, -INFINITY, -INFINITY};
    float lrow[4] = {0.f, 0.f, 0.f, 0.f};

    for (int kt = 0; kt < S_; kt += TK) {
        // ================= Phase A: S = Q @ K  (32 x 256) =================
        float s[4][8];
        #pragma unroll
        for (int a = 0; a < 4; a++)
            #pragma unroll
            for (int j = 0; j < 8; j++) s[a][j] = 0.f;

        for (int dc = 0; dc < D_; dc += 16) {
            __syncthreads();
            {   // load Ks [16 d][256 j]
                int r  = tid >> 4;           // 0..15
                int c0 = (tid & 15) * 16;    // 16 floats per thread
                const float* gsrc = kb_ptr + (size_t)(dc + r) * S_ + kt + c0;
                float* dst = Ks + r * TK + c0;
                #pragma unroll
                for (int i = 0; i < 4; i++)
                    *(float4*)(dst + i * 4) = *(const float4*)(gsrc + i * 4);
            }
            __syncthreads();

            for (int d0 = 0; d0 < 16; d0 += 8) {
                #pragma unroll
                for (int dd = 0; dd < 8; dd++) {
                    int d = d0 + dd;
                    float A4[4];
                    *(float4*)A4 = *(const float4*)(Qt + (dc + d) * 32 + qb4);  // bcast
                    float4 b0 = *(const float4*)(Ks + d * TK + jb);
                    float4 b1 = *(const float4*)(Ks + d * TK + 128 + jb);
                    #pragma unroll
                    for (int a = 0; a < 4; a++) {
                        s[a][0] += A4[a] * b0.x;
                        s[a][1] += A4[a] * b0.y;
                        s[a][2] += A4[a] * b0.z;
                        s[a][3] += A4[a] * b0.w;
                        s[a][4] += A4[a] * b1.x;
                        s[a][5] += A4[a] * b1.y;
                        s[a][6] += A4[a] * b1.z;
                        s[a][7] += A4[a] * b1.w;
                    }
                }
            }
        }

        // ================= Phase B: mask + online softmax ==================
        {
            int4 m0 = *(const int4*)(mb_ptr + kt + jb);
            int4 m1 = *(const int4*)(mb_ptr + kt + 128 + jb);
            #pragma unroll
            for (int a = 0; a < 4; a++) {
                s[a][0] = m0.x ? s[a][0] : -1.0e9f;
                s[a][1] = m0.y ? s[a][1] : -1.0e9f;
                s[a][2] = m0.z ? s[a][2] : -1.0e9f;
                s[a][3] = m0.w ? s[a][3] : -1.0e9f;
                s[a][4] = m1.x ? s[a][4] : -1.0e9f;
                s[a][5] = m1.y ? s[a][5] : -1.0e9f;
                s[a][6] = m1.z ? s[a][6] : -1.0e9f;
                s[a][7] = m1.w ? s[a][7] : -1.0e9f;
            }
        }

        #pragma unroll
        for (int a = 0; a < 4; a++) {
            float rm = fmaxf(fmaxf(fmaxf(s[a][0], s[a][1]), fmaxf(s[a][2], s[a][3])),
                             fmaxf(fmaxf(s[a][4], s[a][5]), fmaxf(s[a][6], s[a][7])));
            #pragma unroll
            for (int off = 16; off > 0; off >>= 1)
                rm = fmaxf(rm, __shfl_xor_sync(0xffffffffu, rm, off));
            float mnew = fmaxf(mrow[a], rm);
            float sc   = __expf(mrow[a] - mnew);
            mrow[a] = mnew;

            float p[8];
            #pragma unroll
            for (int j = 0; j < 8; j++) p[j] = __expf(s[a][j] - mnew);

            float rs = ((p[0] + p[1]) + (p[2] + p[3])) + ((p[4] + p[5]) + (p[6] + p[7]));
            #pragma unroll
            for (int off = 16; off > 0; off >>= 1)
                rs += __shfl_xor_sync(0xffffffffu, rs, off);
            lrow[a] = lrow[a] * sc + rs;

            // P tile (warp-private rows, conflict-free float4 stores, .128-aligned)
            *(float4*)(Ps + (qb4 + a) * PS_STRIDE + jb)       = make_float4(p[0], p[1], p[2], p[3]);
            *(float4*)(Ps + (qb4 + a) * PS_STRIDE + 128 + jb) = make_float4(p[4], p[5], p[6], p[7]);

            #pragma unroll
            for (int c = 0; c < 8; c++) O[a][c] *= sc;
        }
        __syncwarp();

        // ================= Phase C: O += P @ V =================
        for (int jc = 0; jc < TK; jc += 32) {
            __syncthreads();
            {   // load Vs [32 j][256 d]
                int r  = tid >> 3;
                int c0 = (tid & 7) * 32;
                const float4* src = (const float4*)(vb_ptr + (size_t)(kt + jc + r) * D_ + c0);
                float4* dst = (float4*)(Vs + r * D_ + c0);
                #pragma unroll
                for (int i = 0; i < 8; i++) dst[i] = src[i];
            }
            __syncthreads();

            for (int j0 = 0; j0 < 32; j0 += 8) {
                #pragma unroll
                for (int jj = 0; jj < 8; jj++) {
                    int j  = j0 + jj;
                    int jg = jc + j;
                    float4 v0 = *(const float4*)(Vs + j * D_ + jb);         // conflict-free
                    float4 v1 = *(const float4*)(Vs + j * D_ + 128 + jb);   // conflict-free
                    float P4[4];
                    #pragma unroll
                    for (int a = 0; a < 4; a++)
                        P4[a] = Ps[(qb4 + a) * PS_STRIDE + jg];             // scalar bcast
                    #pragma unroll
                    for (int a = 0; a < 4; a++) {
                        O[a][0] += P4[a] * v0.x;
                        O[a][1] += P4[a] * v0.y;
                        O[a][2] += P4[a] * v0.z;
                        O[a][3] += P4[a] * v0.w;
                        O[a][4] += P4[a] * v1.x;
                        O[a][5] += P4[a] * v1.y;
                        O[a][6] += P4[a] * v1.z;
                        O[a][7] += P4[a] * v1.w;
                    }
                }
            }
        }
    }

    // ================= Epilogue: normalize, /16, transpose, store ==========
    float inv[4];
    #pragma unroll
    for (int a = 0; a < 4; a++) inv[a] = 1.f / (lrow[a] * 16.0f);

    __syncthreads();                 // all warps done reading Ps; reuse as T[32][257]
    float* T = Ps;
    #pragma unroll
    for (int a = 0; a < 4; a++) {
        #pragma unroll
        for (int c = 0; c < 4; c++) {
            T[(qb4 + a) * 257 + jb + c]       = O[a][c]     * inv[a];
            T[(qb4 + a) * 257 + 128 + jb + c] = O[a][4 + c] * inv[a];
        }
    }
    __syncthreads();

    // out[b][d][q]: warp w writes d rows {w, w+8, ...}, lanes = consecutive q
    {
        float* ob = out + (size_t)b * D_ * S_ + q0;
        for (int dr = warp; dr < D_; dr += 8)
            ob[(size_t)dr * S_ + lane] = T[lane * 257 + dr];
    }
}

extern "C" void kernel_launch(void* const* d_in, const int* in_sizes, int n_in,
                              void* d_out, int out_size)
{
    (void)in_sizes; (void)n_in; (void)out_size;
    const float* q    = (const float*)d_in[0];
    const float* k    = (const float*)d_in[1];
    const float* v    = (const float*)d_in[2];
    const int*   mask = (const int*)d_in[3];
    float* out = (float*)d_out;

    cudaFuncSetAttribute(attn_flash_fp32,
                         cudaFuncAttributeMaxDynamicSharedMemorySize, SMEM_BYTES);

    dim3 grid(S_ / BQ, B_);
    attn_flash_fp32<<<grid, NT, SMEM_BYTES>>>(q, k, v, mask, out);
}

// round 4
// speedup vs baseline: 1.2174x; 1.1039x over previous
#include <cuda_runtime.h>
#include <math.h>
#include <stdint.h>

#define B_  16
#define S_  2048
#define D_  256
#define BQ  64
#define TK  256
#define KD  32
#define NT  256

// shared layout (floats)
#define KS_STRIDE 260
#define VS_STRIDE 260
#define PS_STRIDE 260
#define QT_OFF 0                                   // Qt [256 d][64 q] = 16384
#define KS_OFF 16384                               // Ks [32 d][260]   = 8320
#define PS_OFF (16384 + 8320)                      // Ps [64 q][260]   = 16640
#define VS_OFF (16384 + 8320 + 16640)              // Vs [32 j][260]   = 8320
#define SMEM_FLOATS (VS_OFF + 32 * VS_STRIDE)
#define SMEM_BYTES  (SMEM_FLOATS * 4)

// packed fp32x2 ops (Blackwell)
#define FMA2(acc, a, b)  asm("fma.rn.f32x2 %0, %1, %2, %0;" : "+l"(acc) : "l"(a), "l"(b))
#define MUL2(d, a, b)    asm("mul.rn.f32x2 %0, %1, %2;" : "=l"(d) : "l"(a), "l"(b))
#define PACK2(d, x, y)   asm("mov.b64 %0, {%1, %2};" : "=l"(d) : "f"(x), "f"(y))
#define UNPACK2(x, y, d) asm("mov.b64 {%0, %1}, %2;" : "=f"(x), "=f"(y) : "l"(d))

__global__ void __launch_bounds__(NT, 1)
attn_flash_f32x2(const float* __restrict__ q,
                 const float* __restrict__ k,
                 const float* __restrict__ v,
                 const int*   __restrict__ mask,
                 float* __restrict__ out)
{
    extern __shared__ float sm[];
    float* Qt = sm + QT_OFF;
    float* Ks = sm + KS_OFF;
    float* Ps = sm + PS_OFF;
    float* Vs = sm + VS_OFF;

    const int tid  = threadIdx.x;
    const int lane = tid & 31;
    const int warp = tid >> 5;
    const int b    = blockIdx.y;
    const int q0   = blockIdx.x * BQ;

    const float* qb_ptr = q + (size_t)b * S_ * D_ + (size_t)q0 * D_;
    const float* kb_ptr = k + (size_t)b * D_ * S_;
    const float* vb_ptr = v + (size_t)b * S_ * D_;
    const int*   mb_ptr = mask + (size_t)b * S_;

    // ---- load Q tile TRANSPOSED into shared: Qt[d][q], q stride 64 ----
    {
        int r  = tid >> 2;           // q row 0..63
        int c0 = (tid & 3) * 64;     // d chunk
        const float4* src = (const float4*)(qb_ptr + (size_t)r * D_ + c0);
        #pragma unroll
        for (int i = 0; i < 16; i++) {
            float4 t = src[i];
            int c = c0 + i * 4;
            Qt[(c + 0) * BQ + r] = t.x;
            Qt[(c + 1) * BQ + r] = t.y;
            Qt[(c + 2) * BQ + r] = t.z;
            Qt[(c + 3) * BQ + r] = t.w;
        }
    }

    const int qb8 = warp * 8;    // this warp owns q rows qb8..qb8+7
    const int jb  = lane * 4;    // lane's j/d columns: jb..+3 and 128+jb..+3

    uint64_t O2[8][4];           // packed output accumulators: 8 q x 8 d
    #pragma unroll
    for (int a = 0; a < 8; a++)
        #pragma unroll
        for (int c = 0; c < 4; c++) O2[a][c] = 0ull;

    float mrow[8], lrow[8];
    #pragma unroll
    for (int a = 0; a < 8; a++) { mrow[a] = -INFINITY; lrow[a] = 0.f; }

    for (int kt = 0; kt < S_; kt += TK) {
        // ================= Phase A: S = Q @ K  (64 x 256) =================
        uint64_t s2[8][4];
        #pragma unroll
        for (int a = 0; a < 8; a++)
            #pragma unroll
            for (int j = 0; j < 4; j++) s2[a][j] = 0ull;

        for (int dc = 0; dc < D_; dc += KD) {
            __syncthreads();
            {   // stage Ks [32 d][256 j] (stride 260)
                int r  = tid >> 3;
                int c0 = (tid & 7) * 32;
                const float* gsrc = kb_ptr + (size_t)(dc + r) * S_ + kt + c0;
                float* dst = Ks + r * KS_STRIDE + c0;
                #pragma unroll
                for (int i = 0; i < 8; i++)
                    *(float4*)(dst + i * 4) = *(const float4*)(gsrc + i * 4);
            }
            __syncthreads();

            #pragma unroll 4
            for (int d = 0; d < KD; d++) {
                float A8[8];
                *(float4*)(A8)     = *(const float4*)(Qt + (dc + d) * BQ + qb8);      // bcast
                *(float4*)(A8 + 4) = *(const float4*)(Qt + (dc + d) * BQ + qb8 + 4);  // bcast
                uint64_t A2[8];
                #pragma unroll
                for (int a = 0; a < 8; a++) PACK2(A2[a], A8[a], A8[a]);

                ulonglong2 b0 = *(const ulonglong2*)(Ks + d * KS_STRIDE + jb);
                ulonglong2 b1 = *(const ulonglong2*)(Ks + d * KS_STRIDE + 128 + jb);
                #pragma unroll
                for (int a = 0; a < 8; a++) {
                    FMA2(s2[a][0], A2[a], b0.x);
                    FMA2(s2[a][1], A2[a], b0.y);
                    FMA2(s2[a][2], A2[a], b1.x);
                    FMA2(s2[a][3], A2[a], b1.y);
                }
            }
        }

        // ================= Phase B: mask + online softmax ==================
        int4 m0 = *(const int4*)(mb_ptr + kt + jb);
        int4 m1 = *(const int4*)(mb_ptr + kt + 128 + jb);

        #pragma unroll
        for (int a = 0; a < 8; a++) {
            float p[8];
            UNPACK2(p[0], p[1], s2[a][0]);
            UNPACK2(p[2], p[3], s2[a][1]);
            UNPACK2(p[4], p[5], s2[a][2]);
            UNPACK2(p[6], p[7], s2[a][3]);

            p[0] = m0.x ? p[0] : -1.0e9f;
            p[1] = m0.y ? p[1] : -1.0e9f;
            p[2] = m0.z ? p[2] : -1.0e9f;
            p[3] = m0.w ? p[3] : -1.0e9f;
            p[4] = m1.x ? p[4] : -1.0e9f;
            p[5] = m1.y ? p[5] : -1.0e9f;
            p[6] = m1.z ? p[6] : -1.0e9f;
            p[7] = m1.w ? p[7] : -1.0e9f;

            float rm = fmaxf(fmaxf(fmaxf(p[0], p[1]), fmaxf(p[2], p[3])),
                             fmaxf(fmaxf(p[4], p[5]), fmaxf(p[6], p[7])));
            #pragma unroll
            for (int off = 16; off > 0; off >>= 1)
                rm = fmaxf(rm, __shfl_xor_sync(0xffffffffu, rm, off));
            float mnew = fmaxf(mrow[a], rm);
            float sc   = __expf(mrow[a] - mnew);
            mrow[a] = mnew;

            #pragma unroll
            for (int j = 0; j < 8; j++) p[j] = __expf(p[j] - mnew);

            float rs = ((p[0] + p[1]) + (p[2] + p[3])) + ((p[4] + p[5]) + (p[6] + p[7]));
            #pragma unroll
            for (int off = 16; off > 0; off >>= 1)
                rs += __shfl_xor_sync(0xffffffffu, rs, off);
            lrow[a] = lrow[a] * sc + rs;

            // P tile rows (warp-private, conflict-free, .128-aligned)
            *(float4*)(Ps + (qb8 + a) * PS_STRIDE + jb)       = make_float4(p[0], p[1], p[2], p[3]);
            *(float4*)(Ps + (qb8 + a) * PS_STRIDE + 128 + jb) = make_float4(p[4], p[5], p[6], p[7]);

            uint64_t sc2; PACK2(sc2, sc, sc);
            #pragma unroll
            for (int c = 0; c < 4; c++) MUL2(O2[a][c], O2[a][c], sc2);
        }
        __syncwarp();

        // ================= Phase C: O += P @ V =================
        for (int jc = 0; jc < TK; jc += 32) {
            __syncthreads();
            {   // stage Vs [32 j][256 d] (stride 260)
                int r  = tid >> 3;
                int c0 = (tid & 7) * 32;
                const float* gsrc = vb_ptr + (size_t)(kt + jc + r) * D_ + c0;
                float* dst = Vs + r * VS_STRIDE + c0;
                #pragma unroll
                for (int i = 0; i < 8; i++)
                    *(float4*)(dst + i * 4) = *(const float4*)(gsrc + i * 4);
            }
            __syncthreads();

            #pragma unroll 2
            for (int j4 = 0; j4 < 8; j4++) {
                float4 Pq[8];
                #pragma unroll
                for (int a = 0; a < 8; a++)
                    Pq[a] = *(const float4*)(Ps + (qb8 + a) * PS_STRIDE + jc + j4 * 4);  // bcast

                #pragma unroll
                for (int ji = 0; ji < 4; ji++) {
                    int j = j4 * 4 + ji;
                    ulonglong2 v0 = *(const ulonglong2*)(Vs + j * VS_STRIDE + jb);
                    ulonglong2 v1 = *(const ulonglong2*)(Vs + j * VS_STRIDE + 128 + jb);
                    #pragma unroll
                    for (int a = 0; a < 8; a++) {
                        float pv = ((const float*)&Pq[a])[ji];
                        uint64_t pv2; PACK2(pv2, pv, pv);
                        FMA2(O2[a][0], pv2, v0.x);
                        FMA2(O2[a][1], pv2, v0.y);
                        FMA2(O2[a][2], pv2, v1.x);
                        FMA2(O2[a][3], pv2, v1.y);
                    }
                }
            }
        }
    }

    // ================= Epilogue: normalize, /16, transpose, store ==========
    float inv[8];
    #pragma unroll
    for (int a = 0; a < 8; a++) inv[a] = 1.f / (lrow[a] * 16.0f);

    __syncthreads();                 // all warps done with Ps; reuse as T[64][257]
    float* T = Ps;
    #pragma unroll
    for (int a = 0; a < 8; a++) {
        float o[8];
        UNPACK2(o[0], o[1], O2[a][0]);
        UNPACK2(o[2], o[3], O2[a][1]);
        UNPACK2(o[4], o[5], O2[a][2]);
        UNPACK2(o[6], o[7], O2[a][3]);
        #pragma unroll
        for (int c = 0; c < 4; c++) {
            T[(qb8 + a) * 257 + jb + c]       = o[c]     * inv[a];
            T[(qb8 + a) * 257 + 128 + jb + c] = o[4 + c] * inv[a];
        }
    }
    __syncthreads();

    // out[b][d][q]: warp w writes d rows {w, w+8, ...}; lanes cover 64 q in 2 halves
    {
        float* ob = out + (size_t)b * D_ * S_ + q0;
        for (int dr = warp; dr < D_; dr += 8) {
            ob[(size_t)dr * S_ + lane]      = T[lane * 257 + dr];
            ob[(size_t)dr * S_ + 32 + lane] = T[(32 + lane) * 257 + dr];
        }
    }
}

extern "C" void kernel_launch(void* const* d_in, const int* in_sizes, int n_in,
                              void* d_out, int out_size)
{
    (void)in_sizes; (void)n_in; (void)out_size;
    const float* q    = (const float*)d_in[0];
    const float* k    = (const float*)d_in[1];
    const float* v    = (const float*)d_in[2];
    const int*   mask = (const int*)d_in[3];
    float* out = (float*)d_out;

    cudaFuncSetAttribute(attn_flash_f32x2,
                         cudaFuncAttributeMaxDynamicSharedMemorySize, SMEM_BYTES);

    dim3 grid(S_ / BQ, B_);
    attn_flash_f32x2<<<grid, NT, SMEM_BYTES>>>(q, k, v, mask, out);
}

// round 6
// speedup vs baseline: 4.1869x; 3.4392x over previous
#include <cuda_runtime.h>
#include <cuda_fp16.h>
#include <math.h>
#include <stdint.h>

#define B_ 16
#define S_ 2048
#define D_ 256
#define NT 256
#define LOG2E 1.4426950408889634f

// ================= fp16 hi/lo split scratch =================
__device__ __half g_Qhi[(size_t)B_*S_*D_];   // [b][q][d]
__device__ __half g_Qlo[(size_t)B_*S_*D_];
__device__ __half g_Kthi[(size_t)B_*S_*D_];  // [b][j][d]
__device__ __half g_Ktlo[(size_t)B_*S_*D_];
__device__ __half g_Vthi[(size_t)B_*S_*D_];  // [b][dv][j]
__device__ __half g_Vtlo[(size_t)B_*S_*D_];

__device__ __forceinline__ uint32_t smem_u32(const void* p) {
    uint32_t a;
    asm("{ .reg .u64 t; cvta.to.shared.u64 t, %1; cvt.u32.u64 %0, t; }" : "=r"(a) : "l"(p));
    return a;
}

// fast exp2 on fma/alu pipes (no MUFU): y <= 0 expected; clamp at -125
__device__ __forceinline__ float exp2p(float y) {
    y = fmaxf(y, -125.f);
    float z = __fadd_rn(y, 12582912.f);            // round-to-nearest int
    int   n = __float_as_int(z) - 0x4B400000;
    float f = __fsub_rn(y, __fadd_rn(z, -12582912.f));   // f in [-0.5, 0.5]
    float p = 1.33335581e-3f;
    p = fmaf(p, f, 9.61812910e-3f);
    p = fmaf(p, f, 5.55041087e-2f);
    p = fmaf(p, f, 2.40226512e-1f);
    p = fmaf(p, f, 6.93147182e-1f);
    p = fmaf(p, f, 1.0f);
    return __int_as_float(__float_as_int(p) + (n << 23));
}

#define LDSM4(r, a) \
    asm volatile("ldmatrix.sync.aligned.m8n8.x4.shared.b16 {%0,%1,%2,%3}, [%4];" \
        : "=r"((r)[0]), "=r"((r)[1]), "=r"((r)[2]), "=r"((r)[3]) : "r"(a))

#define MMA(d, a, b0, b1) \
    asm volatile("mma.sync.aligned.m16n8k16.row.col.f32.f16.f16.f32 " \
        "{%0,%1,%2,%3},{%4,%5,%6,%7},{%8,%9},{%0,%1,%2,%3};" \
        : "+f"((d)[0]), "+f"((d)[1]), "+f"((d)[2]), "+f"((d)[3]) \
        : "r"((a)[0]), "r"((a)[1]), "r"((a)[2]), "r"((a)[3]), "r"(b0), "r"(b1))

#define PACKH2(d, lo, hi) \
    asm("cvt.rn.f16x2.f32 %0, %1, %2;" : "=r"(d) : "f"(hi), "f"(lo))

// ================= prep kernels =================
__global__ void split_q_kernel(const float* __restrict__ q) {
    size_t i = (size_t)blockIdx.x * blockDim.x + threadIdx.x;
    float x = q[i];
    __half h = __float2half_rn(x);
    g_Qhi[i] = h;
    g_Qlo[i] = __float2half_rn(x - __half2float(h));
}

// in [b][R][C] fp32 -> out{hi,lo} [b][C][R] fp16.  which: 0 -> Kt, 1 -> Vt
__global__ void transpose_split_kernel(const float* __restrict__ in, int R, int C, int which) {
    __shared__ float t[32][33];
    int b = blockIdx.z;
    int r0 = blockIdx.y * 32, c0 = blockIdx.x * 32;
    const float* ib = in + (size_t)b * R * C;
    for (int rr = threadIdx.y; rr < 32; rr += 8)
        t[rr][threadIdx.x] = ib[(size_t)(r0 + rr) * C + c0 + threadIdx.x];
    __syncthreads();
    __half* oh = (which ? g_Vthi : g_Kthi) + (size_t)b * R * C;
    __half* ol = (which ? g_Vtlo : g_Ktlo) + (size_t)b * R * C;
    for (int cc = threadIdx.y; cc < 32; cc += 8) {
        float x = t[threadIdx.x][cc];
        __half h = __float2half_rn(x);
        size_t o = (size_t)(c0 + cc) * R + r0 + threadIdx.x;
        oh[o] = h;
        ol[o] = __float2half_rn(x - __half2float(h));
    }
}

// ================= main kernel =================
// smem layout (bytes):
//   Qhi [128][264 halves] at 0          (67584)
//   Qlo                    at 67584     (67584)
//   stage at 135168: K^T hi [64][264] + lo  OR  V^T hi [256][72] + lo
#define QSTR   264
#define QROWB  528
#define QSPLIT 67584
#define OFF_STG 135168
#define KSPLIT 33792
#define VSTR   72
#define VROWB  144
#define VSPLIT 36864
#define SMEM_SZ (OFF_STG + 2*VSPLIT)   // 208896

__global__ void __launch_bounds__(NT, 1)
attn_hmma(const int* __restrict__ mask, float* __restrict__ out)
{
    extern __shared__ char smem[];
    const uint32_t sb = smem_u32(smem);
    const int tid  = threadIdx.x;
    const int lane = tid & 31;
    const int warp = tid >> 5;
    const int b    = blockIdx.y;
    const int q0   = blockIdx.x * 128;

    // ---- stage Q tile (hi, lo), padded stride ----
    #pragma unroll
    for (int split = 0; split < 2; split++) {
        const __half* src = (split ? g_Qlo : g_Qhi) + ((size_t)b * S_ + q0) * D_;
        char* dstb = smem + split * QSPLIT;
        #pragma unroll
        for (int it = 0; it < 16; it++) {
            int idx = tid + it * NT;
            int r = idx >> 5, u = idx & 31;
            uint4 val = *(const uint4*)(src + (size_t)r * D_ + u * 8);
            *(uint4*)(dstb + r * QROWB + u * 16) = val;
        }
    }

    // ---- ldmatrix per-lane address offsets ----
    const int mrow = lane & 7;
    const uint32_t offA  = (uint32_t)((warp * 16 + mrow + (((lane >> 3) & 1) << 3)) * QROWB
                                      + (((lane >> 4) << 3) * 2));
    const int brow  = mrow + ((lane >> 4) << 3);
    const int bcolb = (((lane >> 3) & 1) << 3) * 2;
    const uint32_t offBK = (uint32_t)(brow * QROWB + bcolb);
    const uint32_t offBV = (uint32_t)(brow * VROWB + bcolb);

    const uint32_t aQh = sb + offA;
    const uint32_t aQl = sb + QSPLIT + offA;
    const uint32_t aKh = sb + OFF_STG + offBK;
    const uint32_t aKl = sb + OFF_STG + KSPLIT + offBK;
    const uint32_t aVh = sb + OFF_STG + offBV;
    const uint32_t aVl = sb + OFF_STG + VSPLIT + offBV;

    float O[32][4];
    #pragma unroll
    for (int i = 0; i < 32; i++) { O[i][0] = O[i][1] = O[i][2] = O[i][3] = 0.f; }
    float mr0 = -INFINITY, mr1 = -INFINITY, lr0 = 0.f, lr1 = 0.f;

    const int* mb = mask + (size_t)b * S_;
    const int c2 = (lane & 3) * 2;
    const int g  = lane >> 2;

    for (int jt = 0; jt < 32; jt++) {
        const int kt = jt * 64;

        // ---- stage K^T [64 j][256 d] hi/lo ----
        __syncthreads();
        #pragma unroll
        for (int split = 0; split < 2; split++) {
            const __half* src = (split ? g_Ktlo : g_Kthi) + ((size_t)b * S_ + kt) * D_;
            char* dstb = smem + OFF_STG + split * KSPLIT;
            #pragma unroll
            for (int it = 0; it < 8; it++) {
                int idx = tid + it * NT;
                int r = idx >> 5, u = idx & 31;
                uint4 val = *(const uint4*)(src + (size_t)r * D_ + u * 8);
                *(uint4*)(dstb + r * QROWB + u * 16) = val;
            }
        }
        __syncthreads();

        // ---- GEMM1: S[16 x 64] = Qhi*Khi + Qlo*Khi + Qhi*Klo ----
        float s[8][4];
        #pragma unroll
        for (int i = 0; i < 8; i++) s[i][0] = s[i][1] = s[i][2] = s[i][3] = 0.f;

        #pragma unroll
        for (int kk = 0; kk < 16; kk++) {
            uint32_t ah[4], al[4];
            LDSM4(ah, aQh + kk * 32);
            LDSM4(al, aQl + kk * 32);
            #pragma unroll
            for (int nn = 0; nn < 4; nn++) {
                uint32_t bh[4], bl[4];
                LDSM4(bh, aKh + nn * (16 * QROWB) + kk * 32);
                LDSM4(bl, aKl + nn * (16 * QROWB) + kk * 32);
                MMA(s[2*nn],   ah, bh[0], bh[1]);
                MMA(s[2*nn],   al, bh[0], bh[1]);
                MMA(s[2*nn],   ah, bl[0], bl[1]);
                MMA(s[2*nn+1], ah, bh[2], bh[3]);
                MMA(s[2*nn+1], al, bh[2], bh[3]);
                MMA(s[2*nn+1], ah, bl[2], bl[3]);
            }
        }

        // ---- mask + online softmax (all in regs; exp on FMA pipe) ----
        uint32_t Ph[8][2], Pl[8][2];
        {
            #pragma unroll
            for (int nf = 0; nf < 8; nf++) {
                int2 mv = *(const int2*)(mb + kt + nf * 8 + c2);
                if (mv.x == 0) { s[nf][0] = -1.0e9f; s[nf][2] = -1.0e9f; }
                if (mv.y == 0) { s[nf][1] = -1.0e9f; s[nf][3] = -1.0e9f; }
            }
            float m0 = -INFINITY, m1 = -INFINITY;
            #pragma unroll
            for (int nf = 0; nf < 8; nf++) {
                m0 = fmaxf(m0, fmaxf(s[nf][0], s[nf][1]));
                m1 = fmaxf(m1, fmaxf(s[nf][2], s[nf][3]));
            }
            m0 = fmaxf(m0, __shfl_xor_sync(0xffffffffu, m0, 1));
            m0 = fmaxf(m0, __shfl_xor_sync(0xffffffffu, m0, 2));
            m1 = fmaxf(m1, __shfl_xor_sync(0xffffffffu, m1, 1));
            m1 = fmaxf(m1, __shfl_xor_sync(0xffffffffu, m1, 2));

            float mn0 = fmaxf(mr0, m0), mn1 = fmaxf(mr1, m1);
            float sc0 = exp2p((mr0 - mn0) * LOG2E);
            float sc1 = exp2p((mr1 - mn1) * LOG2E);
            mr0 = mn0; mr1 = mn1;
            float nb0 = -mn0 * LOG2E, nb1 = -mn1 * LOG2E;
            float rs0 = 0.f, rs1 = 0.f;

            #pragma unroll
            for (int nf = 0; nf < 8; nf++) {
                float p0 = exp2p(fmaf(s[nf][0], LOG2E, nb0));
                float p1 = exp2p(fmaf(s[nf][1], LOG2E, nb0));
                float p2 = exp2p(fmaf(s[nf][2], LOG2E, nb1));
                float p3 = exp2p(fmaf(s[nf][3], LOG2E, nb1));
                rs0 += p0 + p1;
                rs1 += p2 + p3;
                uint32_t h01, h23;
                PACKH2(h01, p0, p1);
                PACKH2(h23, p2, p3);
                Ph[nf][0] = h01; Ph[nf][1] = h23;
                float2 f01 = __half22float2(*reinterpret_cast<__half2*>(&h01));
                float2 f23 = __half22float2(*reinterpret_cast<__half2*>(&h23));
                uint32_t l01, l23;
                PACKH2(l01, p0 - f01.x, p1 - f01.y);
                PACKH2(l23, p2 - f23.x, p3 - f23.y);
                Pl[nf][0] = l01; Pl[nf][1] = l23;
            }
            lr0 = lr0 * sc0 + rs0;
            lr1 = lr1 * sc1 + rs1;
            #pragma unroll
            for (int i = 0; i < 32; i++) {
                O[i][0] *= sc0; O[i][1] *= sc0;
                O[i][2] *= sc1; O[i][3] *= sc1;
            }
        }

        // ---- stage V^T [256 dv][64 j] hi/lo (reuse K buffer) ----
        __syncthreads();
        #pragma unroll
        for (int split = 0; split < 2; split++) {
            const __half* src = (split ? g_Vtlo : g_Vthi) + (size_t)b * D_ * S_ + kt;
            char* dstb = smem + OFF_STG + split * VSPLIT;
            #pragma unroll
            for (int it = 0; it < 8; it++) {
                int idx = tid + it * NT;
                int r = idx >> 3, u = idx & 7;
                uint4 val = *(const uint4*)(src + (size_t)r * S_ + u * 8);
                *(uint4*)(dstb + r * VROWB + u * 16) = val;
            }
        }
        __syncthreads();

        // ---- GEMM2: O += P*Vhi + Plo*Vhi + P*Vlo ----
        #pragma unroll
        for (int kk = 0; kk < 4; kk++) {
            uint32_t ah[4] = { Ph[2*kk][0], Ph[2*kk][1], Ph[2*kk+1][0], Ph[2*kk+1][1] };
            uint32_t al[4] = { Pl[2*kk][0], Pl[2*kk][1], Pl[2*kk+1][0], Pl[2*kk+1][1] };
            #pragma unroll
            for (int nn = 0; nn < 16; nn++) {
                uint32_t bh[4], bl[4];
                LDSM4(bh, aVh + nn * (16 * VROWB) + kk * 32);
                LDSM4(bl, aVl + nn * (16 * VROWB) + kk * 32);
                MMA(O[2*nn],   ah, bh[0], bh[1]);
                MMA(O[2*nn],   al, bh[0], bh[1]);
                MMA(O[2*nn],   ah, bl[0], bl[1]);
                MMA(O[2*nn+1], ah, bh[2], bh[3]);
                MMA(O[2*nn+1], al, bh[2], bh[3]);
                MMA(O[2*nn+1], ah, bl[2], bl[3]);
            }
        }
    }

    // ---- epilogue: finish l, normalize by 1/(l*16), store transposed ----
    lr0 += __shfl_xor_sync(0xffffffffu, lr0, 1);
    lr0 += __shfl_xor_sync(0xffffffffu, lr0, 2);
    lr1 += __shfl_xor_sync(0xffffffffu, lr1, 1);
    lr1 += __shfl_xor_sync(0xffffffffu, lr1, 2);
    float inv0 = 1.f / (lr0 * 16.0f);
    float inv1 = 1.f / (lr1 * 16.0f);

    float* ob = out + (size_t)b * D_ * S_;
    const int qg = q0 + warp * 16 + g;
    #pragma unroll
    for (int nn = 0; nn < 32; nn++) {
        int dv = nn * 8 + c2;
        ob[(size_t)dv * S_ + qg]           = O[nn][0] * inv0;
        ob[(size_t)(dv + 1) * S_ + qg]     = O[nn][1] * inv0;
        ob[(size_t)dv * S_ + qg + 8]       = O[nn][2] * inv1;
        ob[(size_t)(dv + 1) * S_ + qg + 8] = O[nn][3] * inv1;
    }
}

// ================= launcher =================
extern "C" void kernel_launch(void* const* d_in, const int* in_sizes, int n_in,
                              void* d_out, int out_size)
{
    (void)in_sizes; (void)n_in; (void)out_size;
    const float* q    = (const float*)d_in[0];
    const float* k    = (const float*)d_in[1];
    const float* v    = (const float*)d_in[2];
    const int*   mask = (const int*)d_in[3];
    float* out = (float*)d_out;

    split_q_kernel<<<(B_ * S_ * D_) / 256, 256>>>(q);
    transpose_split_kernel<<<dim3(S_ / 32, D_ / 32, B_), dim3(32, 8)>>>(k, D_, S_, 0);
    transpose_split_kernel<<<dim3(D_ / 32, S_ / 32, B_), dim3(32, 8)>>>(v, S_, D_, 1);

    cudaFuncSetAttribute(attn_hmma, cudaFuncAttributeMaxDynamicSharedMemorySize, SMEM_SZ);
    attn_hmma<<<dim3(S_ / 128, B_), NT, SMEM_SZ>>>(mask, out);
}

// round 7
// speedup vs baseline: 4.9828x; 1.1901x over previous
#include <cuda_runtime.h>
#include <cuda_fp16.h>
#include <math.h>
#include <stdint.h>

#define B_ 16
#define S_ 2048
#define D_ 256
#define NT 256
#define LOG2E 1.4426950408889634f

// ================= fp16 hi/lo split scratch =================
__device__ __half g_Qhi[(size_t)B_*S_*D_];   // [b][q][d]
__device__ __half g_Qlo[(size_t)B_*S_*D_];
__device__ __half g_Kthi[(size_t)B_*S_*D_];  // [b][j][d]
__device__ __half g_Ktlo[(size_t)B_*S_*D_];
__device__ __half g_Vthi[(size_t)B_*S_*D_];  // [b][dv][j]
__device__ __half g_Vtlo[(size_t)B_*S_*D_];

__device__ __forceinline__ uint32_t smem_u32(const void* p) {
    uint32_t a;
    asm("{ .reg .u64 t; cvta.to.shared.u64 t, %1; cvt.u32.u64 %0, t; }" : "=r"(a) : "l"(p));
    return a;
}

// fast exp2 on fma/alu pipes (no MUFU): y <= 0 expected; clamp at -125
__device__ __forceinline__ float exp2p(float y) {
    y = fmaxf(y, -125.f);
    float z = __fadd_rn(y, 12582912.f);            // round-to-nearest int
    int   n = __float_as_int(z) - 0x4B400000;
    float f = __fsub_rn(y, __fadd_rn(z, -12582912.f));   // f in [-0.5, 0.5]
    float p = 1.33335581e-3f;
    p = fmaf(p, f, 9.61812910e-3f);
    p = fmaf(p, f, 5.55041087e-2f);
    p = fmaf(p, f, 2.40226512e-1f);
    p = fmaf(p, f, 6.93147182e-1f);
    p = fmaf(p, f, 1.0f);
    return __int_as_float(__float_as_int(p) + (n << 23));
}

#define LDSM4(r, a) \
    asm volatile("ldmatrix.sync.aligned.m8n8.x4.shared.b16 {%0,%1,%2,%3}, [%4];" \
        : "=r"((r)[0]), "=r"((r)[1]), "=r"((r)[2]), "=r"((r)[3]) : "r"(a))

#define MMA(d, a, b0, b1) \
    asm volatile("mma.sync.aligned.m16n8k16.row.col.f32.f16.f16.f32 " \
        "{%0,%1,%2,%3},{%4,%5,%6,%7},{%8,%9},{%0,%1,%2,%3};" \
        : "+f"((d)[0]), "+f"((d)[1]), "+f"((d)[2]), "+f"((d)[3]) \
        : "r"((a)[0]), "r"((a)[1]), "r"((a)[2]), "r"((a)[3]), "r"(b0), "r"(b1))

#define PACKH2(d, lo, hi) \
    asm("cvt.rn.f16x2.f32 %0, %1, %2;" : "=r"(d) : "f"(hi), "f"(lo))

#define CPASYNC16(dst, src) \
    asm volatile("cp.async.cg.shared.global [%0], [%1], 16;" :: "r"(dst), "l"(src))
#define CPCOMMIT() asm volatile("cp.async.commit_group;" ::: "memory")
#define CPWAIT0()  asm volatile("cp.async.wait_group 0;" ::: "memory")

// ================= prep kernels =================
__global__ void split_q_kernel(const float* __restrict__ q) {
    size_t i = (size_t)blockIdx.x * blockDim.x + threadIdx.x;
    float x = q[i];
    __half h = __float2half_rn(x);
    g_Qhi[i] = h;
    g_Qlo[i] = __float2half_rn(x - __half2float(h));
}

// in [b][R][C] fp32 -> out{hi,lo} [b][C][R] fp16.  which: 0 -> Kt, 1 -> Vt
__global__ void transpose_split_kernel(const float* __restrict__ in, int R, int C, int which) {
    __shared__ float t[32][33];
    int b = blockIdx.z;
    int r0 = blockIdx.y * 32, c0 = blockIdx.x * 32;
    const float* ib = in + (size_t)b * R * C;
    for (int rr = threadIdx.y; rr < 32; rr += 8)
        t[rr][threadIdx.x] = ib[(size_t)(r0 + rr) * C + c0 + threadIdx.x];
    __syncthreads();
    __half* oh = (which ? g_Vthi : g_Kthi) + (size_t)b * R * C;
    __half* ol = (which ? g_Vtlo : g_Ktlo) + (size_t)b * R * C;
    for (int cc = threadIdx.y; cc < 32; cc += 8) {
        float x = t[threadIdx.x][cc];
        __half h = __float2half_rn(x);
        size_t o = (size_t)(c0 + cc) * R + r0 + threadIdx.x;
        oh[o] = h;
        ol[o] = __float2half_rn(x - __half2float(h));
    }
}

// ================= main kernel =================
#define QSTR   264
#define QROWB  528
#define QSPLIT 67584
#define OFF_STG 135168
#define KSPLIT 33792
#define VSTR   72
#define VROWB  144
#define VSPLIT 36864
#define SMEM_SZ (OFF_STG + 2*VSPLIT)   // 208896

__global__ void __launch_bounds__(NT, 1)
attn_hmma(const int* __restrict__ mask, float* __restrict__ out)
{
    extern __shared__ char smem[];
    const uint32_t sb = smem_u32(smem);
    const int tid  = threadIdx.x;
    const int lane = tid & 31;
    const int warp = tid >> 5;
    const int b    = blockIdx.y;
    const int q0   = blockIdx.x * 128;

    // ---- stage Q tile (hi, lo), padded stride, via cp.async ----
    #pragma unroll
    for (int split = 0; split < 2; split++) {
        const __half* src = (split ? g_Qlo : g_Qhi) + ((size_t)b * S_ + q0) * D_;
        uint32_t dstb = sb + split * QSPLIT;
        #pragma unroll
        for (int it = 0; it < 16; it++) {
            int idx = tid + it * NT;
            int r = idx >> 5, u = idx & 31;
            CPASYNC16(dstb + r * QROWB + u * 16, src + (size_t)r * D_ + u * 8);
        }
    }
    CPCOMMIT();

    // ---- ldmatrix per-lane address offsets ----
    const int mrow = lane & 7;
    const uint32_t offA  = (uint32_t)((warp * 16 + mrow + (((lane >> 3) & 1) << 3)) * QROWB
                                      + (((lane >> 4) << 3) * 2));
    const int brow  = mrow + ((lane >> 4) << 3);
    const int bcolb = (((lane >> 3) & 1) << 3) * 2;
    const uint32_t offBK = (uint32_t)(brow * QROWB + bcolb);
    const uint32_t offBV = (uint32_t)(brow * VROWB + bcolb);

    const uint32_t aQh = sb + offA;
    const uint32_t aQl = sb + QSPLIT + offA;
    const uint32_t aKh = sb + OFF_STG + offBK;
    const uint32_t aKl = sb + OFF_STG + KSPLIT + offBK;
    const uint32_t aVh = sb + OFF_STG + offBV;
    const uint32_t aVl = sb + OFF_STG + VSPLIT + offBV;

    float O[32][4];
    #pragma unroll
    for (int i = 0; i < 32; i++) { O[i][0] = O[i][1] = O[i][2] = O[i][3] = 0.f; }
    float mr0 = -INFINITY, mr1 = -INFINITY, lr0 = 0.f, lr1 = 0.f;

    const int* mb = mask + (size_t)b * S_;
    const int c2 = (lane & 3) * 2;
    const int g  = lane >> 2;

    for (int jt = 0; jt < 32; jt++) {
        const int kt = jt * 64;

        // ---- stage K^T [64 j][256 d] hi/lo ----
        __syncthreads();
        #pragma unroll
        for (int split = 0; split < 2; split++) {
            const __half* src = (split ? g_Ktlo : g_Kthi) + ((size_t)b * S_ + kt) * D_;
            uint32_t dstb = sb + OFF_STG + split * KSPLIT;
            #pragma unroll
            for (int it = 0; it < 8; it++) {
                int idx = tid + it * NT;
                int r = idx >> 5, u = idx & 31;
                CPASYNC16(dstb + r * QROWB + u * 16, src + (size_t)r * D_ + u * 8);
            }
        }
        CPCOMMIT();
        CPWAIT0();
        __syncthreads();

        // ---- GEMM1: S[16 x 64] = Qhi*Khi + Qlo*Khi + Qhi*Klo ----
        float s[8][4];
        #pragma unroll
        for (int i = 0; i < 8; i++) s[i][0] = s[i][1] = s[i][2] = s[i][3] = 0.f;

        #pragma unroll
        for (int kk = 0; kk < 16; kk++) {
            uint32_t ah[4], al[4];
            LDSM4(ah, aQh + kk * 32);
            LDSM4(al, aQl + kk * 32);
            #pragma unroll
            for (int nn = 0; nn < 4; nn++) {
                uint32_t bh[4], bl[4];
                LDSM4(bh, aKh + nn * (16 * QROWB) + kk * 32);
                LDSM4(bl, aKl + nn * (16 * QROWB) + kk * 32);
                MMA(s[2*nn],   ah, bh[0], bh[1]);
                MMA(s[2*nn],   al, bh[0], bh[1]);
                MMA(s[2*nn],   ah, bl[0], bl[1]);
                MMA(s[2*nn+1], ah, bh[2], bh[3]);
                MMA(s[2*nn+1], al, bh[2], bh[3]);
                MMA(s[2*nn+1], ah, bl[2], bl[3]);
            }
        }

        // ---- mask + online softmax (regs only; exp on FMA pipe) ----
        uint32_t Ph[8][2];
        {
            #pragma unroll
            for (int nf = 0; nf < 8; nf++) {
                int2 mv = *(const int2*)(mb + kt + nf * 8 + c2);
                if (mv.x == 0) { s[nf][0] = -1.0e9f; s[nf][2] = -1.0e9f; }
                if (mv.y == 0) { s[nf][1] = -1.0e9f; s[nf][3] = -1.0e9f; }
            }
            float m0 = -INFINITY, m1 = -INFINITY;
            #pragma unroll
            for (int nf = 0; nf < 8; nf++) {
                m0 = fmaxf(m0, fmaxf(s[nf][0], s[nf][1]));
                m1 = fmaxf(m1, fmaxf(s[nf][2], s[nf][3]));
            }
            m0 = fmaxf(m0, __shfl_xor_sync(0xffffffffu, m0, 1));
            m0 = fmaxf(m0, __shfl_xor_sync(0xffffffffu, m0, 2));
            m1 = fmaxf(m1, __shfl_xor_sync(0xffffffffu, m1, 1));
            m1 = fmaxf(m1, __shfl_xor_sync(0xffffffffu, m1, 2));

            float mn0 = fmaxf(mr0, m0), mn1 = fmaxf(mr1, m1);
            float sc0 = exp2p((mr0 - mn0) * LOG2E);
            float sc1 = exp2p((mr1 - mn1) * LOG2E);
            mr0 = mn0; mr1 = mn1;
            float nb0 = -mn0 * LOG2E, nb1 = -mn1 * LOG2E;
            float rs0 = 0.f, rs1 = 0.f;

            #pragma unroll
            for (int nf = 0; nf < 8; nf++) {
                float p0 = exp2p(fmaf(s[nf][0], LOG2E, nb0));
                float p1 = exp2p(fmaf(s[nf][1], LOG2E, nb0));
                float p2 = exp2p(fmaf(s[nf][2], LOG2E, nb1));
                float p3 = exp2p(fmaf(s[nf][3], LOG2E, nb1));
                rs0 += p0 + p1;
                rs1 += p2 + p3;
                PACKH2(Ph[nf][0], p0, p1);
                PACKH2(Ph[nf][1], p2, p3);
            }
            lr0 = lr0 * sc0 + rs0;
            lr1 = lr1 * sc1 + rs1;

            // skip the 128-FMUL rescale when no lane's max moved
            if (__any_sync(0xffffffffu, (sc0 != 1.0f) || (sc1 != 1.0f))) {
                #pragma unroll
                for (int i = 0; i < 32; i++) {
                    O[i][0] *= sc0; O[i][1] *= sc0;
                    O[i][2] *= sc1; O[i][3] *= sc1;
                }
            }
        }

        // ---- stage V^T [256 dv][64 j] hi/lo (reuse K buffer) ----
        __syncthreads();
        #pragma unroll
        for (int split = 0; split < 2; split++) {
            const __half* src = (split ? g_Vtlo : g_Vthi) + (size_t)b * D_ * S_ + kt;
            uint32_t dstb = sb + OFF_STG + split * VSPLIT;
            #pragma unroll
            for (int it = 0; it < 8; it++) {
                int idx = tid + it * NT;
                int r = idx >> 3, u = idx & 7;
                CPASYNC16(dstb + r * VROWB + u * 16, src + (size_t)r * S_ + u * 8);
            }
        }
        CPCOMMIT();
        CPWAIT0();
        __syncthreads();

        // ---- GEMM2: O += P*Vhi + P*Vlo  (Plo term dropped; err ~2e-4) ----
        #pragma unroll
        for (int kk = 0; kk < 4; kk++) {
            uint32_t ah[4] = { Ph[2*kk][0], Ph[2*kk][1], Ph[2*kk+1][0], Ph[2*kk+1][1] };
            #pragma unroll
            for (int nn = 0; nn < 16; nn++) {
                uint32_t bh[4], bl[4];
                LDSM4(bh, aVh + nn * (16 * VROWB) + kk * 32);
                LDSM4(bl, aVl + nn * (16 * VROWB) + kk * 32);
                MMA(O[2*nn],   ah, bh[0], bh[1]);
                MMA(O[2*nn],   ah, bl[0], bl[1]);
                MMA(O[2*nn+1], ah, bh[2], bh[3]);
                MMA(O[2*nn+1], ah, bl[2], bl[3]);
            }
        }
    }

    // ---- epilogue: finish l, normalize by 1/(l*16), store transposed ----
    lr0 += __shfl_xor_sync(0xffffffffu, lr0, 1);
    lr0 += __shfl_xor_sync(0xffffffffu, lr0, 2);
    lr1 += __shfl_xor_sync(0xffffffffu, lr1, 1);
    lr1 += __shfl_xor_sync(0xffffffffu, lr1, 2);
    float inv0 = 1.f / (lr0 * 16.0f);
    float inv1 = 1.f / (lr1 * 16.0f);

    float* ob = out + (size_t)b * D_ * S_;
    const int qg = q0 + warp * 16 + g;
    #pragma unroll
    for (int nn = 0; nn < 32; nn++) {
        int dv = nn * 8 + c2;
        ob[(size_t)dv * S_ + qg]           = O[nn][0] * inv0;
        ob[(size_t)(dv + 1) * S_ + qg]     = O[nn][1] * inv0;
        ob[(size_t)dv * S_ + qg + 8]       = O[nn][2] * inv1;
        ob[(size_t)(dv + 1) * S_ + qg + 8] = O[nn][3] * inv1;
    }
}

// ================= launcher =================
extern "C" void kernel_launch(void* const* d_in, const int* in_sizes, int n_in,
                              void* d_out, int out_size)
{
    (void)in_sizes; (void)n_in; (void)out_size;
    const float* q    = (const float*)d_in[0];
    const float* k    = (const float*)d_in[1];
    const float* v    = (const float*)d_in[2];
    const int*   mask = (const int*)d_in[3];
    float* out = (float*)d_out;

    split_q_kernel<<<(B_ * S_ * D_) / 256, 256>>>(q);
    transpose_split_kernel<<<dim3(S_ / 32, D_ / 32, B_), dim3(32, 8)>>>(k, D_, S_, 0);
    transpose_split_kernel<<<dim3(D_ / 32, S_ / 32, B_), dim3(32, 8)>>>(v, S_, D_, 1);

    cudaFuncSetAttribute(attn_hmma, cudaFuncAttributeMaxDynamicSharedMemorySize, SMEM_SZ);
    attn_hmma<<<dim3(S_ / 128, B_), NT, SMEM_SZ>>>(mask, out);
}

// round 8
// speedup vs baseline: 7.1105x; 1.4270x over previous
#include <cuda_runtime.h>
#include <cuda_fp16.h>
#include <math.h>
#include <stdint.h>

#define B_ 16
#define S_ 2048
#define D_ 256
#define NT 256
#define LOG2E 1.4426950408889634f

// ================= fp16 hi/lo split scratch =================
__device__ __half g_Qhi[(size_t)B_*S_*D_];   // [b][q][d]
__device__ __half g_Qlo[(size_t)B_*S_*D_];
__device__ __half g_Kthi[(size_t)B_*S_*D_];  // [b][j][d]
__device__ __half g_Ktlo[(size_t)B_*S_*D_];
__device__ __half g_Vthi[(size_t)B_*S_*D_];  // [b][dv][j]

__device__ __forceinline__ uint32_t smem_u32(const void* p) {
    uint32_t a;
    asm("{ .reg .u64 t; cvta.to.shared.u64 t, %1; cvt.u32.u64 %0, t; }" : "=r"(a) : "l"(p));
    return a;
}

// fast exp2 on fma/alu pipes (no MUFU)
__device__ __forceinline__ float exp2p(float y) {
    y = fmaxf(y, -125.f);
    float z = __fadd_rn(y, 12582912.f);
    int   n = __float_as_int(z) - 0x4B400000;
    float f = __fsub_rn(y, __fadd_rn(z, -12582912.f));
    float p = 1.33335581e-3f;
    p = fmaf(p, f, 9.61812910e-3f);
    p = fmaf(p, f, 5.55041087e-2f);
    p = fmaf(p, f, 2.40226512e-1f);
    p = fmaf(p, f, 6.93147182e-1f);
    p = fmaf(p, f, 1.0f);
    return __int_as_float(__float_as_int(p) + (n << 23));
}

#define LDSM4(r, a) \
    asm volatile("ldmatrix.sync.aligned.m8n8.x4.shared.b16 {%0,%1,%2,%3}, [%4];" \
        : "=r"((r)[0]), "=r"((r)[1]), "=r"((r)[2]), "=r"((r)[3]) : "r"(a))

#define MMA(d, a, b0, b1) \
    asm volatile("mma.sync.aligned.m16n8k16.row.col.f32.f16.f16.f32 " \
        "{%0,%1,%2,%3},{%4,%5,%6,%7},{%8,%9},{%0,%1,%2,%3};" \
        : "+f"((d)[0]), "+f"((d)[1]), "+f"((d)[2]), "+f"((d)[3]) \
        : "r"((a)[0]), "r"((a)[1]), "r"((a)[2]), "r"((a)[3]), "r"(b0), "r"(b1))

#define PACKH2(d, lo, hi) \
    asm("cvt.rn.f16x2.f32 %0, %1, %2;" : "=r"(d) : "f"(hi), "f"(lo))

#define CPASYNC16(dst, src) \
    asm volatile("cp.async.cg.shared.global [%0], [%1], 16;" :: "r"(dst), "l"(src))
#define CPCOMMIT() asm volatile("cp.async.commit_group;" ::: "memory")
#define CPWAIT0()  asm volatile("cp.async.wait_group 0;" ::: "memory")

// ================= prep kernels =================
__global__ void split_q_kernel(const float* __restrict__ q) {
    size_t i = (size_t)blockIdx.x * blockDim.x + threadIdx.x;
    float x = q[i];
    __half h = __float2half_rn(x);
    g_Qhi[i] = h;
    g_Qlo[i] = __float2half_rn(x - __half2float(h));
}

// in [b][R][C] fp32 -> transposed fp16. which=0: K (hi+lo), which=1: V (hi only)
__global__ void transpose_split_kernel(const float* __restrict__ in, int R, int C, int which) {
    __shared__ float t[32][33];
    int b = blockIdx.z;
    int r0 = blockIdx.y * 32, c0 = blockIdx.x * 32;
    const float* ib = in + (size_t)b * R * C;
    for (int rr = threadIdx.y; rr < 32; rr += 8)
        t[rr][threadIdx.x] = ib[(size_t)(r0 + rr) * C + c0 + threadIdx.x];
    __syncthreads();
    __half* oh = (which ? g_Vthi : g_Kthi) + (size_t)b * R * C;
    for (int cc = threadIdx.y; cc < 32; cc += 8) {
        float x = t[threadIdx.x][cc];
        __half h = __float2half_rn(x);
        size_t o = (size_t)(c0 + cc) * R + r0 + threadIdx.x;
        oh[o] = h;
        if (which == 0)
            g_Ktlo[(size_t)b * R * C + o] = __float2half_rn(x - __half2float(h));
    }
}

// ================= main kernel =================
// swizzled smem: 16B unit (r,u) at r*ROW + ((u ^ (r&7)) << 4)
#define ROWQ   512
#define QSP    65536
#define OFF_K  131072
#define KSP    32768
#define OFF_V  196608
#define ROWV   128
#define SMEM_SZ 229376

__global__ void __launch_bounds__(NT, 1)
attn_hmma(const int* __restrict__ mask, float* __restrict__ out)
{
    extern __shared__ char smem[];
    const uint32_t sb = smem_u32(smem);
    const int tid  = threadIdx.x;
    const int lane = tid & 31;
    const int warp = tid >> 5;
    const int b    = blockIdx.y;
    const int q0   = blockIdx.x * 128;

    const __half* qh_src = g_Qhi  + ((size_t)b * S_ + q0) * D_;
    const __half* ql_src = g_Qlo  + ((size_t)b * S_ + q0) * D_;
    const __half* kh_b   = g_Kthi + (size_t)b * S_ * D_;
    const __half* kl_b   = g_Ktlo + (size_t)b * S_ * D_;
    const __half* vh_b   = g_Vthi + (size_t)b * D_ * S_;

    // ---- prologue: issue Q (hi/lo) + K(0) ----
    #pragma unroll
    for (int it = 0; it < 16; it++) {                   // Q: 8192 units, 2 splits
        int idx = tid + it * NT;
        int r = idx >> 5, u = idx & 31;
        uint32_t d0 = sb + r * ROWQ + (((u ^ (r & 7)) ) << 4);
        CPASYNC16(d0,       qh_src + (size_t)r * D_ + u * 8);
        CPASYNC16(d0 + QSP, ql_src + (size_t)r * D_ + u * 8);
    }
    #pragma unroll
    for (int it = 0; it < 8; it++) {                    // K(0): 2048 units x2
        int idx = tid + it * NT;
        int r = idx >> 5, u = idx & 31;
        uint32_t d0 = sb + OFF_K + r * ROWQ + ((u ^ (r & 7)) << 4);
        CPASYNC16(d0,       kh_b + (size_t)r * D_ + u * 8);
        CPASYNC16(d0 + KSP, kl_b + (size_t)r * D_ + u * 8);
    }
    CPCOMMIT();

    // ---- ldmatrix lane geometry + swizzle base tables ----
    const int mrow = lane & 7;
    const int rowA = warp * 16 + mrow + (((lane >> 3) & 1) << 3);
    const int hiA  = lane >> 4;
    const int rowB = mrow + ((lane >> 4) << 3);
    const int cB   = (lane >> 3) & 1;

    uint32_t aQh[4], aQl[4], aKh[4], aKl[4], aVh[4];
    #pragma unroll
    for (int m = 0; m < 4; m++) {
        uint32_t swA = (uint32_t)(((2 * m + hiA) ^ mrow) << 4);
        uint32_t swB = (uint32_t)(((2 * m + cB)  ^ mrow) << 4);
        aQh[m] = sb + rowA * ROWQ + swA;
        aQl[m] = aQh[m] + QSP;
        aKh[m] = sb + OFF_K + rowB * ROWQ + swB;
        aKl[m] = aKh[m] + KSP;
        aVh[m] = sb + OFF_V + rowB * ROWV + swB;
    }

    float O[32][4];
    #pragma unroll
    for (int i = 0; i < 32; i++) { O[i][0] = O[i][1] = O[i][2] = O[i][3] = 0.f; }
    float mr0 = -INFINITY, mr1 = -INFINITY, lr0 = 0.f, lr1 = 0.f;

    const int* mb = mask + (size_t)b * S_;
    const int c2 = (lane & 3) * 2;
    const int g  = lane >> 2;

    for (int jt = 0; jt < 32; jt++) {
        const int kt = jt * 64;

        CPWAIT0();             // K(jt) ready (and Q on first iter)
        __syncthreads();       // all warps done GEMM2(jt-1) -> V buffer free

        // ---- issue V(jt) load (overlaps GEMM1) ----
        #pragma unroll
        for (int it = 0; it < 8; it++) {               // V: 2048 units
            int idx = tid + it * NT;
            int r = idx >> 3, u = idx & 7;
            uint32_t d0 = sb + OFF_V + r * ROWV + ((u ^ (r & 7)) << 4);
            CPASYNC16(d0, vh_b + (size_t)r * S_ + kt + u * 8);
        }
        CPCOMMIT();

        // ---- GEMM1: S[16x64] = Qhi*Khi + Qlo*Khi + Qhi*Klo ----
        float s[8][4];
        #pragma unroll
        for (int i = 0; i < 8; i++) s[i][0] = s[i][1] = s[i][2] = s[i][3] = 0.f;

        #pragma unroll
        for (int kk = 0; kk < 16; kk++) {
            const int ko = (kk >> 2) * 128;
            const int m  = kk & 3;
            uint32_t ah[4], al[4];
            LDSM4(ah, aQh[m] + ko);
            LDSM4(al, aQl[m] + ko);
            #pragma unroll
            for (int nn = 0; nn < 4; nn++) {
                uint32_t bh[4], bl[4];
                LDSM4(bh, aKh[m] + nn * (16 * ROWQ) + ko);
                LDSM4(bl, aKl[m] + nn * (16 * ROWQ) + ko);
                MMA(s[2*nn],   ah, bh[0], bh[1]);
                MMA(s[2*nn],   al, bh[0], bh[1]);
                MMA(s[2*nn],   ah, bl[0], bl[1]);
                MMA(s[2*nn+1], ah, bh[2], bh[3]);
                MMA(s[2*nn+1], al, bh[2], bh[3]);
                MMA(s[2*nn+1], ah, bl[2], bl[3]);
            }
        }

        // ---- mask + online softmax ----
        uint32_t Ph[8][2];
        {
            #pragma unroll
            for (int nf = 0; nf < 8; nf++) {
                int2 mv = *(const int2*)(mb + kt + nf * 8 + c2);
                if (mv.x == 0) { s[nf][0] = -1.0e9f; s[nf][2] = -1.0e9f; }
                if (mv.y == 0) { s[nf][1] = -1.0e9f; s[nf][3] = -1.0e9f; }
            }
            float m0 = -INFINITY, m1 = -INFINITY;
            #pragma unroll
            for (int nf = 0; nf < 8; nf++) {
                m0 = fmaxf(m0, fmaxf(s[nf][0], s[nf][1]));
                m1 = fmaxf(m1, fmaxf(s[nf][2], s[nf][3]));
            }
            m0 = fmaxf(m0, __shfl_xor_sync(0xffffffffu, m0, 1));
            m0 = fmaxf(m0, __shfl_xor_sync(0xffffffffu, m0, 2));
            m1 = fmaxf(m1, __shfl_xor_sync(0xffffffffu, m1, 1));
            m1 = fmaxf(m1, __shfl_xor_sync(0xffffffffu, m1, 2));

            float mn0 = fmaxf(mr0, m0), mn1 = fmaxf(mr1, m1);
            float sc0 = exp2p((mr0 - mn0) * LOG2E);
            float sc1 = exp2p((mr1 - mn1) * LOG2E);
            mr0 = mn0; mr1 = mn1;
            float nb0 = -mn0 * LOG2E, nb1 = -mn1 * LOG2E;
            float rs0 = 0.f, rs1 = 0.f;

            #pragma unroll
            for (int nf = 0; nf < 8; nf++) {
                float p0 = exp2p(fmaf(s[nf][0], LOG2E, nb0));
                float p1 = exp2p(fmaf(s[nf][1], LOG2E, nb0));
                float p2 = exp2p(fmaf(s[nf][2], LOG2E, nb1));
                float p3 = exp2p(fmaf(s[nf][3], LOG2E, nb1));
                rs0 += p0 + p1;
                rs1 += p2 + p3;
                PACKH2(Ph[nf][0], p0, p1);
                PACKH2(Ph[nf][1], p2, p3);
            }
            lr0 = lr0 * sc0 + rs0;
            lr1 = lr1 * sc1 + rs1;

            if (__any_sync(0xffffffffu, (sc0 != 1.0f) || (sc1 != 1.0f))) {
                #pragma unroll
                for (int i = 0; i < 32; i++) {
                    O[i][0] *= sc0; O[i][1] *= sc0;
                    O[i][2] *= sc1; O[i][3] *= sc1;
                }
            }
        }

        CPWAIT0();             // V(jt) ready
        __syncthreads();       // all warps done GEMM1 -> K buffer free

        // ---- issue K(jt+1) load (overlaps GEMM2) ----
        if (jt + 1 < 32) {
            const __half* khs = kh_b + (size_t)(kt + 64) * D_;
            const __half* kls = kl_b + (size_t)(kt + 64) * D_;
            #pragma unroll
            for (int it = 0; it < 8; it++) {
                int idx = tid + it * NT;
                int r = idx >> 5, u = idx & 31;
                uint32_t d0 = sb + OFF_K + r * ROWQ + ((u ^ (r & 7)) << 4);
                CPASYNC16(d0,       khs + (size_t)r * D_ + u * 8);
                CPASYNC16(d0 + KSP, kls + (size_t)r * D_ + u * 8);
            }
            CPCOMMIT();
        }

        // ---- GEMM2: O += P * Vhi ----
        #pragma unroll
        for (int kk = 0; kk < 4; kk++) {
            uint32_t ah[4] = { Ph[2*kk][0], Ph[2*kk][1], Ph[2*kk+1][0], Ph[2*kk+1][1] };
            #pragma unroll
            for (int nn = 0; nn < 16; nn++) {
                uint32_t bh[4];
                LDSM4(bh, aVh[kk] + nn * (16 * ROWV));
                MMA(O[2*nn],   ah, bh[0], bh[1]);
                MMA(O[2*nn+1], ah, bh[2], bh[3]);
            }
        }
    }

    // ---- epilogue ----
    lr0 += __shfl_xor_sync(0xffffffffu, lr0, 1);
    lr0 += __shfl_xor_sync(0xffffffffu, lr0, 2);
    lr1 += __shfl_xor_sync(0xffffffffu, lr1, 1);
    lr1 += __shfl_xor_sync(0xffffffffu, lr1, 2);
    float inv0 = 1.f / (lr0 * 16.0f);
    float inv1 = 1.f / (lr1 * 16.0f);

    float* ob = out + (size_t)b * D_ * S_;
    const int qg = q0 + warp * 16 + g;
    #pragma unroll
    for (int nn = 0; nn < 32; nn++) {
        int dv = nn * 8 + c2;
        ob[(size_t)dv * S_ + qg]           = O[nn][0] * inv0;
        ob[(size_t)(dv + 1) * S_ + qg]     = O[nn][1] * inv0;
        ob[(size_t)dv * S_ + qg + 8]       = O[nn][2] * inv1;
        ob[(size_t)(dv + 1) * S_ + qg + 8] = O[nn][3] * inv1;
    }
}

// ================= launcher =================
extern "C" void kernel_launch(void* const* d_in, const int* in_sizes, int n_in,
                              void* d_out, int out_size)
{
    (void)in_sizes; (void)n_in; (void)out_size;
    const float* q    = (const float*)d_in[0];
    const float* k    = (const float*)d_in[1];
    const float* v    = (const float*)d_in[2];
    const int*   mask = (const int*)d_in[3];
    float* out = (float*)d_out;

    split_q_kernel<<<(B_ * S_ * D_) / 256, 256>>>(q);
    transpose_split_kernel<<<dim3(S_ / 32, D_ / 32, B_), dim3(32, 8)>>>(k, D_, S_, 0);
    transpose_split_kernel<<<dim3(D_ / 32, S_ / 32, B_), dim3(32, 8)>>>(v, S_, D_, 1);

    cudaFuncSetAttribute(attn_hmma, cudaFuncAttributeMaxDynamicSharedMemorySize, SMEM_SZ);
    attn_hmma<<<dim3(S_ / 128, B_), NT, SMEM_SZ>>>(mask, out);
}